// round 14
// baseline (speedup 1.0000x reference)
#include <cuda_runtime.h>
#include <cuda_bf16.h>
#include <stdint.h>
#include <math.h>

// ---------------- problem constants ----------------
#define BB 32
#define HH 56
#define WW 56
#define CC 192
#define WS 7
#define SHIFT 3
#define HEADS 6
#define HID 768
#define NN 49
#define NWIN 64
#define HD 32
#define TOK (BB*HH*WW)   // 100352

// weight scratch offsets (elements)
#define W_QKV 0
#define W_PROJ 110592
#define W_FC1 147456
#define W_FC2 294912
#define W_TOTAL 442368

// ---------------- scratch ----------------
__device__ __nv_bfloat16 g_hwin[(size_t)TOK * CC];       // LN out (bf16 A-operand)
__device__ float         g_qkv [(size_t)TOK * 3 * CC];   // qkv (fp32, attn reads)
__device__ __nv_bfloat16 g_obuf[(size_t)TOK * CC];       // attn out (bf16 A-operand)
__device__ float         g_x1  [(size_t)TOK * CC];       // x + attn branch (fp32)
__device__ __nv_bfloat16 g_m1  [(size_t)TOK * HID];      // gelu out (bf16 A-operand)
__device__ __nv_bfloat16 g_wt  [W_TOTAL];                // weights, transposed [N][K] bf16
__device__ float         g_bm  [(size_t)HEADS * NWIN * NN * 50];  // bias+mask folded

__device__ __forceinline__ void cp16(void* sp, const void* gp) {
    unsigned int sa = (unsigned int)__cvta_generic_to_shared(sp);
    asm volatile("cp.async.ca.shared.global [%0], [%1], 16;" :: "r"(sa), "l"(gp));
}

__device__ __forceinline__ __nv_bfloat162 pack_bf2(float lo, float hi) {
    return __floats2bfloat162_rn(lo, hi);
}

#define MMA_BF(acc, A0, A1, A2, A3, B0, B1)                                 \
    asm("mma.sync.aligned.m16n8k16.row.col.f32.bf16.bf16.f32 "              \
        "{%0,%1,%2,%3}, {%4,%5,%6,%7}, {%8,%9}, {%0,%1,%2,%3};"             \
        : "+f"(acc[0]), "+f"(acc[1]), "+f"(acc[2]), "+f"(acc[3])            \
        : "r"(A0), "r"(A1), "r"(A2), "r"(A3), "r"(B0), "r"(B1))

// ---------------- weight transpose + bf16: wt[n][k] = bf16(W[k][n]) ----------------
__global__ void round_wt_kernel(const float* __restrict__ a, const float* __restrict__ b,
                                const float* __restrict__ c, const float* __restrict__ d,
                                __nv_bfloat16* __restrict__ o)
{
    int i = blockIdx.x * 256 + threadIdx.x;
    if (i >= W_TOTAL) return;
    const float* src; int off, K_, N_;
    if (i < W_PROJ)      { src = a; off = W_QKV;  K_ = 192; N_ = 576; }
    else if (i < W_FC1)  { src = b; off = W_PROJ; K_ = 192; N_ = 192; }
    else if (i < W_FC2)  { src = c; off = W_FC1;  K_ = 192; N_ = 768; }
    else                 { src = d; off = W_FC2;  K_ = 768; N_ = 192; }
    int il = i - off;
    int n = il / K_, k = il % K_;
    o[i] = __float2bfloat16(src[(size_t)k * N_ + n]);
}

// ---------------- bias+mask fold: bm[head][wi][i][j(pad 50)] ----------------
__global__ void bm_kernel(const float* __restrict__ bias_table,
                          const int*   __restrict__ rel_index,
                          const float* __restrict__ mask,
                          float* __restrict__ bm)
{
    int idx = blockIdx.x * 256 + threadIdx.x;
    if (idx >= HEADS * NWIN * NN * NN) return;
    int head = idx / (NWIN * NN * NN);
    int r    = idx % (NWIN * NN * NN);
    int wi   = r / (NN * NN);
    int ij   = r % (NN * NN);
    bm[((size_t)(head * NWIN + wi) * NN + ij / NN) * 50 + ij % NN] =
        bias_table[rel_index[ij] * HEADS + head] + mask[(size_t)wi * NN * NN + ij];
}

// ---------------- LayerNorm (1 warp/row) -> bf16, optional shift+window gather ----------------
template<bool WINDOW_MAP>
__global__ void ln_kernel(const float* __restrict__ x,
                          const float* __restrict__ w,
                          const float* __restrict__ b,
                          __nv_bfloat16* __restrict__ out)
{
    int row  = blockIdx.x * (blockDim.x >> 5) + (threadIdx.x >> 5);
    int lane = threadIdx.x & 31;
    if (row >= TOK) return;

    int src;
    if (WINDOW_MAP) {
        int widx = row / NN;
        int n    = row % NN;
        int bb   = widx / NWIN;
        int wi   = widx % NWIN;
        int wh   = wi / (WW / WS);
        int ww   = wi % (WW / WS);
        int hs   = wh * WS + n / WS;
        int ws   = ww * WS + n % WS;
        int h0   = (hs + SHIFT) % HH;
        int w0   = (ws + SHIFT) % WW;
        src = (bb * HH + h0) * WW + w0;
    } else {
        src = row;
    }

    const float* xr = x + (size_t)src * CC;
    float2 v[3];
    float s = 0.f;
#pragma unroll
    for (int i = 0; i < 3; i++) {
        v[i] = *(const float2*)(xr + 2 * lane + 64 * i);
        s += v[i].x + v[i].y;
    }
#pragma unroll
    for (int o = 16; o; o >>= 1) s += __shfl_xor_sync(0xffffffffu, s, o);
    float mu = s * (1.0f / CC);
    float vs = 0.f;
#pragma unroll
    for (int i = 0; i < 3; i++) {
        float d0 = v[i].x - mu, d1 = v[i].y - mu;
        vs += d0 * d0 + d1 * d1;
    }
#pragma unroll
    for (int o = 16; o; o >>= 1) vs += __shfl_xor_sync(0xffffffffu, vs, o);
    float rstd = rsqrtf(vs * (1.0f / CC) + 1e-5f);

    __nv_bfloat16* orow = out + (size_t)row * CC;
#pragma unroll
    for (int i = 0; i < 3; i++) {
        int c = 2 * lane + 64 * i;
        float y0 = (v[i].x - mu) * rstd * w[c]     + b[c];
        float y1 = (v[i].y - mu) * rstd * w[c + 1] + b[c + 1];
        *(__nv_bfloat162*)(orow + c) = pack_bf2(y0, y1);
    }
}

// ---------------- bf16 tensor-core GEMM, cp.async double-buffered ----------------
// BM=128, BN=64, BK=32. 128 threads = 4 warps (2m x 2n), warp tile 64x32.
template<int K, int EPI>
__global__ __launch_bounds__(128)
void gemm_bf(const __nv_bfloat16* __restrict__ A, const __nv_bfloat16* __restrict__ Wt,
             const float* __restrict__ bias, const float* __restrict__ aux,
             float* __restrict__ Cf, __nv_bfloat16* __restrict__ Cb, int Nc)
{
    __shared__ __nv_bfloat16 As[2][128 * 40];
    __shared__ __nv_bfloat16 Bs[2][64 * 40];

    int tid  = threadIdx.x;
    int lane = tid & 31;
    int warp = tid >> 5;
    int g = lane >> 2;
    int q = lane & 3;
    int wm = (warp >> 1) * 64;
    int wn = (warp & 1) * 32;
    int m0 = blockIdx.y * 128;
    int n0 = blockIdx.x * 64;

    int a_m  = tid >> 2;
    int a_kc = (tid & 3) * 8;
    int b_n  = tid >> 2;
    int b_kc = (tid & 3) * 8;

    float acc[4][4][4] = {};
    constexpr int KT = K / 32;

#define ISSUE(kt, st) do {                                                          \
        __nv_bfloat16* as_ = As[st];                                                \
        __nv_bfloat16* bs_ = Bs[st];                                                \
        _Pragma("unroll")                                                           \
        for (int j = 0; j < 4; j++) {                                               \
            int m_ = a_m + 32 * j;                                                  \
            cp16(as_ + m_ * 40 + a_kc, A + (size_t)(m0 + m_) * K + (kt) * 32 + a_kc); \
        }                                                                           \
        _Pragma("unroll")                                                           \
        for (int j = 0; j < 2; j++) {                                               \
            int n_ = b_n + 32 * j;                                                  \
            cp16(bs_ + n_ * 40 + b_kc, Wt + (size_t)(n0 + n_) * K + (kt) * 32 + b_kc); \
        }                                                                           \
        asm volatile("cp.async.commit_group;");                                     \
    } while (0)

    ISSUE(0, 0);
    for (int kt = 0; kt < KT; kt++) {
        if (kt + 1 < KT) { ISSUE(kt + 1, (kt + 1) & 1); }
        else             { asm volatile("cp.async.commit_group;"); }
        asm volatile("cp.async.wait_group 1;");
        __syncthreads();

        const unsigned int* as32 = (const unsigned int*)As[kt & 1];
        const unsigned int* bs32 = (const unsigned int*)Bs[kt & 1];
#pragma unroll
        for (int ks = 0; ks < 2; ks++) {
            int kw = ks * 8;
            unsigned int a[4][4], b[4][2];
#pragma unroll
            for (int mi = 0; mi < 4; mi++) {
                int mm = wm + mi * 16 + g;
                a[mi][0] = as32[mm * 20 + kw + q];
                a[mi][1] = as32[(mm + 8) * 20 + kw + q];
                a[mi][2] = as32[mm * 20 + kw + q + 4];
                a[mi][3] = as32[(mm + 8) * 20 + kw + q + 4];
            }
#pragma unroll
            for (int ni = 0; ni < 4; ni++) {
                int nn = wn + ni * 8 + g;
                b[ni][0] = bs32[nn * 20 + kw + q];
                b[ni][1] = bs32[nn * 20 + kw + q + 4];
            }
#pragma unroll
            for (int mi = 0; mi < 4; mi++)
#pragma unroll
                for (int ni = 0; ni < 4; ni++)
                    MMA_BF(acc[mi][ni], a[mi][0], a[mi][1], a[mi][2], a[mi][3],
                           b[ni][0], b[ni][1]);
        }
        __syncthreads();
    }
#undef ISSUE

    // ---- epilogue ----
#pragma unroll
    for (int mi = 0; mi < 4; mi++) {
#pragma unroll
        for (int h = 0; h < 2; h++) {
            int row = m0 + wm + mi * 16 + g + h * 8;
            size_t base;
            if (EPI == 2) {
                int widx = row / NN;
                int n    = row % NN;
                int bimg = widx >> 6;
                int wi   = widx & 63;
                int hs = (wi >> 3) * WS + n / WS;
                int ws = (wi & 7) * WS + n % WS;
                int h2 = hs + SHIFT; if (h2 >= HH) h2 -= HH;
                int w2 = ws + SHIFT; if (w2 >= WW) w2 -= WW;
                base = (size_t)((bimg * HH + h2) * WW + w2) * CC;
            } else {
                base = (size_t)row * Nc;
            }
#pragma unroll
            for (int ni = 0; ni < 4; ni++) {
                int col = n0 + wn + ni * 8 + 2 * q;
                float c0 = acc[mi][ni][2 * h + 0] + bias[col];
                float c1 = acc[mi][ni][2 * h + 1] + bias[col + 1];
                size_t idx = base + col;
                if (EPI == 1) {
                    c0 = 0.5f * c0 * (1.0f + erff(c0 * 0.70710678118654752f));
                    c1 = 0.5f * c1 * (1.0f + erff(c1 * 0.70710678118654752f));
                    *(__nv_bfloat162*)(Cb + idx) = pack_bf2(c0, c1);
                } else {
                    if (EPI == 2 || EPI == 3) {
                        float2 av = *(const float2*)(aux + idx);
                        c0 += av.x; c1 += av.y;
                    }
                    float2 o; o.x = c0; o.y = c1;
                    *(float2*)(Cf + idx) = o;
                }
            }
        }
    }
}

// ---------------- attention (SIMT, LDS.64-vectorized): block per (window, head) ----------------
#define QST (HD + 2)   // 34 floats, float2-aligned rows
__global__ __launch_bounds__(128)
void attn_kernel(const float* __restrict__ qkv,
                 const float* __restrict__ bm,
                 __nv_bfloat16* __restrict__ obuf)
{
    int blk  = blockIdx.x;
    int head = blk % HEADS;
    int widx = blk / HEADS;
    int wi   = widx % NWIN;

    __shared__ float q[NN][QST], k[NN][QST], v[NN][QST];
    __shared__ float s[NN][NN + 1];

    int tid = threadIdx.x;
    const float scale = 0.17677669529663687f;

    for (int idx = tid; idx < NN * HD; idx += 128) {
        int i = idx >> 5;
        int d = idx & 31;
        size_t base = (size_t)(widx * NN + i) * (3 * CC);
        q[i][d] = qkv[base + head * HD + d] * scale;
        k[i][d] = qkv[base + CC + head * HD + d];
        v[i][d] = qkv[base + 2 * CC + head * HD + d];
    }
    __syncthreads();

    // ---- scores: unit (i, jg), float2 over d ----
    const float* bmb = bm + (size_t)(head * NWIN + wi) * NN * 50;
    for (int u = tid; u < NN * 7; u += 128) {
        int i  = u / 7;
        int jg = u % 7;
        float a[7] = {};
#pragma unroll
        for (int d2 = 0; d2 < 16; d2++) {
            float2 qd = *(const float2*)&q[i][2 * d2];
#pragma unroll
            for (int jj = 0; jj < 7; jj++) {
                float2 kd = *(const float2*)&k[jg * 7 + jj][2 * d2];
                a[jj] = fmaf(qd.x, kd.x, a[jj]);
                a[jj] = fmaf(qd.y, kd.y, a[jj]);
            }
        }
#pragma unroll
        for (int jj = 0; jj < 7; jj++) {
            int j = jg * 7 + jj;
            s[i][j] = a[jj] + bmb[i * 50 + j];
        }
    }
    __syncthreads();

    // ---- softmax: warp per row ----
    int warp = tid >> 5, lane = tid & 31;
    for (int i = warp; i < NN; i += 4) {
        float x1 = s[i][lane];
        float x2 = (lane + 32 < NN) ? s[i][lane + 32] : -1e30f;
        float m = fmaxf(x1, x2);
#pragma unroll
        for (int o = 16; o; o >>= 1) m = fmaxf(m, __shfl_xor_sync(0xffffffffu, m, o));
        float e1 = __expf(x1 - m);
        float e2 = (lane + 32 < NN) ? __expf(x2 - m) : 0.f;
        float sum = e1 + e2;
#pragma unroll
        for (int o = 16; o; o >>= 1) sum += __shfl_xor_sync(0xffffffffu, sum, o);
        float inv = 1.0f / sum;
        s[i][lane] = e1 * inv;
        if (lane + 32 < NN) s[i][lane + 32] = e2 * inv;
    }
    __syncthreads();

    // ---- O = S @ V : half-warp per row, float2 over d ----
    int half = lane >> 4;          // 0/1
    int dl   = (lane & 15) * 2;    // d pair
    for (int r = warp * 2 + half; r < NN; r += 8) {
        float2 acc; acc.x = 0.f; acc.y = 0.f;
#pragma unroll
        for (int j = 0; j < NN; j++) {
            float sj = s[r][j];
            float2 vj = *(const float2*)&v[j][dl];
            acc.x = fmaf(sj, vj.x, acc.x);
            acc.y = fmaf(sj, vj.y, acc.y);
        }
        *(__nv_bfloat162*)&obuf[(size_t)(widx * NN + r) * CC + head * HD + dl] =
            pack_bf2(acc.x, acc.y);
    }
}

// ---------------- launch ----------------
extern "C" void kernel_launch(void* const* d_in, const int* in_sizes, int n_in,
                              void* d_out, int out_size)
{
    const float* x          = (const float*)d_in[0];
    const float* norm1_w    = (const float*)d_in[1];
    const float* norm1_b    = (const float*)d_in[2];
    const float* qkv_w      = (const float*)d_in[3];
    const float* qkv_b      = (const float*)d_in[4];
    const float* bias_table = (const float*)d_in[5];
    const float* proj_w     = (const float*)d_in[6];
    const float* proj_b     = (const float*)d_in[7];
    const float* norm2_w    = (const float*)d_in[8];
    const float* norm2_b    = (const float*)d_in[9];
    const float* fc1_w      = (const float*)d_in[10];
    const float* fc1_b      = (const float*)d_in[11];
    const float* fc2_w      = (const float*)d_in[12];
    const float* fc2_b      = (const float*)d_in[13];
    const float* attn_mask  = (const float*)d_in[14];
    const int*   rel_index  = (const int*)  d_in[15];
    float* out = (float*)d_out;

    __nv_bfloat16 *hwin, *obuf, *m1, *wt;
    float *qkv, *x1, *bm;
    cudaGetSymbolAddress((void**)&hwin, g_hwin);
    cudaGetSymbolAddress((void**)&qkv,  g_qkv);
    cudaGetSymbolAddress((void**)&obuf, g_obuf);
    cudaGetSymbolAddress((void**)&x1,   g_x1);
    cudaGetSymbolAddress((void**)&m1,   g_m1);
    cudaGetSymbolAddress((void**)&wt,   g_wt);
    cudaGetSymbolAddress((void**)&bm,   g_bm);

    // 0. weights -> bf16 transposed; fold bias+mask
    round_wt_kernel<<<(W_TOTAL + 255) / 256, 256>>>(qkv_w, proj_w, fc1_w, fc2_w, wt);
    bm_kernel<<<(HEADS * NWIN * NN * NN + 255) / 256, 256>>>(bias_table, rel_index, attn_mask, bm);

    // 1. LN1 + shift + window partition -> bf16
    ln_kernel<true><<<TOK / 8, 256>>>(x, norm1_w, norm1_b, hwin);

    // 2. QKV gemm -> fp32
    gemm_bf<192,0><<<dim3(9, TOK / 128), 128>>>(hwin, wt + W_QKV, qkv_b, nullptr, qkv, nullptr, 576);

    // 3. attention -> bf16
    attn_kernel<<<(TOK / NN) * HEADS, 128>>>(qkv, bm, obuf);

    // 4. proj gemm + window-reverse scatter + residual(x) -> x1 (fp32)
    gemm_bf<192,2><<<dim3(3, TOK / 128), 128>>>(obuf, wt + W_PROJ, proj_b, x, x1, nullptr, CC);

    // 5. LN2 -> bf16
    ln_kernel<false><<<TOK / 8, 256>>>(x1, norm2_w, norm2_b, hwin);

    // 6. fc1 + gelu -> bf16
    gemm_bf<192,1><<<dim3(12, TOK / 128), 128>>>(hwin, wt + W_FC1, fc1_b, nullptr, nullptr, m1, HID);

    // 7. fc2 + residual(x1) -> out (fp32)
    gemm_bf<768,3><<<dim3(3, TOK / 128), 128>>>(m1, wt + W_FC2, fc2_b, x1, out, nullptr, CC);
}

// round 15
// speedup vs baseline: 1.1047x; 1.1047x over previous
#include <cuda_runtime.h>
#include <cuda_bf16.h>
#include <stdint.h>
#include <math.h>

// ---------------- problem constants ----------------
#define BB 32
#define HH 56
#define WW 56
#define CC 192
#define WS 7
#define SHIFT 3
#define HEADS 6
#define HID 768
#define NN 49
#define NWIN 64
#define HD 32
#define TOK (BB*HH*WW)   // 100352

// weight scratch offsets (elements)
#define W_QKV 0
#define W_PROJ 110592
#define W_FC1 147456
#define W_FC2 294912
#define W_TOTAL 442368

// ---------------- scratch ----------------
__device__ __nv_bfloat16 g_hwin[(size_t)TOK * CC];
__device__ float         g_qkv [(size_t)TOK * 3 * CC];
__device__ __nv_bfloat16 g_obuf[(size_t)TOK * CC];
__device__ float         g_x1  [(size_t)TOK * CC];
__device__ __nv_bfloat16 g_m1  [(size_t)TOK * HID];
__device__ __nv_bfloat16 g_wt  [W_TOTAL];

__device__ __forceinline__ void cp16(void* sp, const void* gp) {
    unsigned int sa = (unsigned int)__cvta_generic_to_shared(sp);
    asm volatile("cp.async.ca.shared.global [%0], [%1], 16;" :: "r"(sa), "l"(gp));
}

__device__ __forceinline__ __nv_bfloat162 pack_bf2(float lo, float hi) {
    return __floats2bfloat162_rn(lo, hi);
}

__device__ __forceinline__ void ldsm4(unsigned int& r0, unsigned int& r1,
                                      unsigned int& r2, unsigned int& r3,
                                      unsigned int addr) {
    asm volatile("ldmatrix.sync.aligned.m8n8.x4.shared.b16 {%0,%1,%2,%3}, [%4];"
                 : "=r"(r0), "=r"(r1), "=r"(r2), "=r"(r3) : "r"(addr));
}

#define MMA_BF(acc, A0, A1, A2, A3, B0, B1)                                 \
    asm("mma.sync.aligned.m16n8k16.row.col.f32.bf16.bf16.f32 "              \
        "{%0,%1,%2,%3}, {%4,%5,%6,%7}, {%8,%9}, {%0,%1,%2,%3};"             \
        : "+f"(acc[0]), "+f"(acc[1]), "+f"(acc[2]), "+f"(acc[3])            \
        : "r"(A0), "r"(A1), "r"(A2), "r"(A3), "r"(B0), "r"(B1))

// ---------------- weight transpose + bf16: wt[n][k] = bf16(W[k][n]) ----------------
__global__ void round_wt_kernel(const float* __restrict__ a, const float* __restrict__ b,
                                const float* __restrict__ c, const float* __restrict__ d,
                                __nv_bfloat16* __restrict__ o)
{
    int i = blockIdx.x * 256 + threadIdx.x;
    if (i >= W_TOTAL) return;
    const float* src; int off, K_, N_;
    if (i < W_PROJ)      { src = a; off = W_QKV;  K_ = 192; N_ = 576; }
    else if (i < W_FC1)  { src = b; off = W_PROJ; K_ = 192; N_ = 192; }
    else if (i < W_FC2)  { src = c; off = W_FC1;  K_ = 192; N_ = 768; }
    else                 { src = d; off = W_FC2;  K_ = 768; N_ = 192; }
    int il = i - off;
    int n = il / K_, k = il % K_;
    o[i] = __float2bfloat16(src[(size_t)k * N_ + n]);
}

// ---------------- LayerNorm (1 warp/row) -> bf16, optional shift+window gather ----------------
template<bool WINDOW_MAP>
__global__ void ln_kernel(const float* __restrict__ x,
                          const float* __restrict__ w,
                          const float* __restrict__ b,
                          __nv_bfloat16* __restrict__ out)
{
    int row  = blockIdx.x * (blockDim.x >> 5) + (threadIdx.x >> 5);
    int lane = threadIdx.x & 31;
    if (row >= TOK) return;

    int src;
    if (WINDOW_MAP) {
        int widx = row / NN;
        int n    = row % NN;
        int bb   = widx / NWIN;
        int wi   = widx % NWIN;
        int wh   = wi / (WW / WS);
        int ww   = wi % (WW / WS);
        int hs   = wh * WS + n / WS;
        int ws   = ww * WS + n % WS;
        int h0   = (hs + SHIFT) % HH;
        int w0   = (ws + SHIFT) % WW;
        src = (bb * HH + h0) * WW + w0;
    } else {
        src = row;
    }

    const float* xr = x + (size_t)src * CC;
    float2 v[3];
    float s = 0.f;
#pragma unroll
    for (int i = 0; i < 3; i++) {
        v[i] = *(const float2*)(xr + 2 * lane + 64 * i);
        s += v[i].x + v[i].y;
    }
#pragma unroll
    for (int o = 16; o; o >>= 1) s += __shfl_xor_sync(0xffffffffu, s, o);
    float mu = s * (1.0f / CC);
    float vs = 0.f;
#pragma unroll
    for (int i = 0; i < 3; i++) {
        float d0 = v[i].x - mu, d1 = v[i].y - mu;
        vs += d0 * d0 + d1 * d1;
    }
#pragma unroll
    for (int o = 16; o; o >>= 1) vs += __shfl_xor_sync(0xffffffffu, vs, o);
    float rstd = rsqrtf(vs * (1.0f / CC) + 1e-5f);

    __nv_bfloat16* orow = out + (size_t)row * CC;
#pragma unroll
    for (int i = 0; i < 3; i++) {
        int c = 2 * lane + 64 * i;
        float y0 = (v[i].x - mu) * rstd * w[c]     + b[c];
        float y1 = (v[i].y - mu) * rstd * w[c + 1] + b[c + 1];
        *(__nv_bfloat162*)(orow + c) = pack_bf2(y0, y1);
    }
}

// ---------------- bf16 tensor-core GEMM, cp.async double-buffered, ldmatrix frags ----------------
// BM=128, BN=64, BK=32. 128 threads = 4 warps (2m x 2n), warp tile 64x32.
template<int K, int EPI>
__global__ __launch_bounds__(128)
void gemm_bf(const __nv_bfloat16* __restrict__ A, const __nv_bfloat16* __restrict__ Wt,
             const float* __restrict__ bias, const float* __restrict__ aux,
             float* __restrict__ Cf, __nv_bfloat16* __restrict__ Cb, int Nc)
{
    __shared__ __align__(16) __nv_bfloat16 As[2][128 * 40];
    __shared__ __align__(16) __nv_bfloat16 Bs[2][64 * 40];

    int tid  = threadIdx.x;
    int lane = tid & 31;
    int warp = tid >> 5;
    int g = lane >> 2;
    int q = lane & 3;
    int wm = (warp >> 1) * 64;
    int wn = (warp & 1) * 32;
    int m0 = blockIdx.y * 128;
    int n0 = blockIdx.x * 64;

    int a_m  = tid >> 2;
    int a_kc = (tid & 3) * 8;
    int b_n  = tid >> 2;
    int b_kc = (tid & 3) * 8;

    // ldmatrix per-lane element offsets (bf16 units)
    int a_ld_off = (wm + (lane & 15)) * 40 + (lane >> 4) * 8;           // + mi*16*40 + ks*16
    int b_ld_off = (wn + (lane >> 4) * 8 + (lane & 7)) * 40
                 + ((lane >> 3) & 1) * 8;                               // + pair*16*40 + ks*16

    float acc[4][4][4] = {};
    constexpr int KT = K / 32;

#define ISSUE(kt, st) do {                                                          \
        __nv_bfloat16* as_ = As[st];                                                \
        __nv_bfloat16* bs_ = Bs[st];                                                \
        _Pragma("unroll")                                                           \
        for (int j = 0; j < 4; j++) {                                               \
            int m_ = a_m + 32 * j;                                                  \
            cp16(as_ + m_ * 40 + a_kc, A + (size_t)(m0 + m_) * K + (kt) * 32 + a_kc); \
        }                                                                           \
        _Pragma("unroll")                                                           \
        for (int j = 0; j < 2; j++) {                                               \
            int n_ = b_n + 32 * j;                                                  \
            cp16(bs_ + n_ * 40 + b_kc, Wt + (size_t)(n0 + n_) * K + (kt) * 32 + b_kc); \
        }                                                                           \
        asm volatile("cp.async.commit_group;");                                     \
    } while (0)

    ISSUE(0, 0);
    for (int kt = 0; kt < KT; kt++) {
        if (kt + 1 < KT) { ISSUE(kt + 1, (kt + 1) & 1); }
        else             { asm volatile("cp.async.commit_group;"); }
        asm volatile("cp.async.wait_group 1;");
        __syncthreads();

        unsigned int as_base = (unsigned int)__cvta_generic_to_shared(As[kt & 1]);
        unsigned int bs_base = (unsigned int)__cvta_generic_to_shared(Bs[kt & 1]);
#pragma unroll
        for (int ks = 0; ks < 2; ks++) {
            unsigned int a[4][4], b[4][2];
#pragma unroll
            for (int mi = 0; mi < 4; mi++)
                ldsm4(a[mi][0], a[mi][1], a[mi][2], a[mi][3],
                      as_base + 2u * (a_ld_off + mi * 16 * 40 + ks * 16));
            // B: first ldsm4 -> n-tiles {0,1}, second -> {2,3}
            ldsm4(b[0][0], b[0][1], b[1][0], b[1][1],
                  bs_base + 2u * (b_ld_off + ks * 16));
            ldsm4(b[2][0], b[2][1], b[3][0], b[3][1],
                  bs_base + 2u * (b_ld_off + 16 * 40 + ks * 16));
#pragma unroll
            for (int mi = 0; mi < 4; mi++)
#pragma unroll
                for (int ni = 0; ni < 4; ni++)
                    MMA_BF(acc[mi][ni], a[mi][0], a[mi][1], a[mi][2], a[mi][3],
                           b[ni][0], b[ni][1]);
        }
        __syncthreads();
    }
#undef ISSUE

    // ---- epilogue ----
#pragma unroll
    for (int mi = 0; mi < 4; mi++) {
#pragma unroll
        for (int h = 0; h < 2; h++) {
            int row = m0 + wm + mi * 16 + g + h * 8;
            size_t base;
            if (EPI == 2) {
                int widx = row / NN;
                int n    = row % NN;
                int bimg = widx >> 6;
                int wi   = widx & 63;
                int hs = (wi >> 3) * WS + n / WS;
                int ws = (wi & 7) * WS + n % WS;
                int h2 = hs + SHIFT; if (h2 >= HH) h2 -= HH;
                int w2 = ws + SHIFT; if (w2 >= WW) w2 -= WW;
                base = (size_t)((bimg * HH + h2) * WW + w2) * CC;
            } else {
                base = (size_t)row * Nc;
            }
#pragma unroll
            for (int ni = 0; ni < 4; ni++) {
                int col = n0 + wn + ni * 8 + 2 * q;
                float c0 = acc[mi][ni][2 * h + 0] + bias[col];
                float c1 = acc[mi][ni][2 * h + 1] + bias[col + 1];
                size_t idx = base + col;
                if (EPI == 1) {
                    c0 = 0.5f * c0 * (1.0f + erff(c0 * 0.70710678118654752f));
                    c1 = 0.5f * c1 * (1.0f + erff(c1 * 0.70710678118654752f));
                    *(__nv_bfloat162*)(Cb + idx) = pack_bf2(c0, c1);
                } else {
                    if (EPI == 2 || EPI == 3) {
                        float2 av = *(const float2*)(aux + idx);
                        c0 += av.x; c1 += av.y;
                    }
                    float2 o; o.x = c0; o.y = c1;
                    *(float2*)(Cf + idx) = o;
                }
            }
        }
    }
}

// ---------------- attention (SIMT, round-13 proven version) ----------------
__global__ __launch_bounds__(128)
void attn_kernel(const float* __restrict__ qkv,
                 const float* __restrict__ bias_table,
                 const int*   __restrict__ rel_index,
                 const float* __restrict__ mask,
                 __nv_bfloat16* __restrict__ obuf)
{
    int blk  = blockIdx.x;
    int head = blk % HEADS;
    int widx = blk / HEADS;
    int wi   = widx % NWIN;

    __shared__ float q[NN][HD + 1], k[NN][HD + 1], v[NN][HD + 1];
    __shared__ float s[NN][NN + 1];

    int tid = threadIdx.x;
    const float scale = 0.17677669529663687f;

    for (int idx = tid; idx < NN * HD; idx += 128) {
        int i = idx >> 5;
        int d = idx & 31;
        size_t base = (size_t)(widx * NN + i) * (3 * CC);
        q[i][d] = qkv[base + head * HD + d] * scale;
        k[i][d] = qkv[base + CC + head * HD + d];
        v[i][d] = qkv[base + 2 * CC + head * HD + d];
    }
    __syncthreads();

    const float* mrow = mask + (size_t)wi * NN * NN;
    for (int u = tid; u < NN * 7; u += 128) {
        int i  = u / 7;
        int jg = u % 7;
        float a[7] = {};
#pragma unroll
        for (int d = 0; d < HD; d++) {
            float qd = q[i][d];
#pragma unroll
            for (int jj = 0; jj < 7; jj++)
                a[jj] = fmaf(qd, k[jg * 7 + jj][d], a[jj]);
        }
#pragma unroll
        for (int jj = 0; jj < 7; jj++) {
            int j = jg * 7 + jj;
            a[jj] += bias_table[rel_index[i * NN + j] * HEADS + head] + mrow[i * NN + j];
            s[i][j] = a[jj];
        }
    }
    __syncthreads();

    int warp = tid >> 5, lane = tid & 31;
    for (int i = warp; i < NN; i += 4) {
        float x1 = s[i][lane];
        float x2 = (lane + 32 < NN) ? s[i][lane + 32] : -1e30f;
        float m = fmaxf(x1, x2);
#pragma unroll
        for (int o = 16; o; o >>= 1) m = fmaxf(m, __shfl_xor_sync(0xffffffffu, m, o));
        float e1 = __expf(x1 - m);
        float e2 = (lane + 32 < NN) ? __expf(x2 - m) : 0.f;
        float sum = e1 + e2;
#pragma unroll
        for (int o = 16; o; o >>= 1) sum += __shfl_xor_sync(0xffffffffu, sum, o);
        float inv = 1.0f / sum;
        s[i][lane] = e1 * inv;
        if (lane + 32 < NN) s[i][lane + 32] = e2 * inv;
    }
    __syncthreads();

    for (int r = warp; r < NN; r += 4) {
        float a0 = 0.f, a1 = 0.f;
#pragma unroll
        for (int j = 0; j < 48; j += 2) {
            a0 = fmaf(s[r][j],     v[j][lane],     a0);
            a1 = fmaf(s[r][j + 1], v[j + 1][lane], a1);
        }
        a0 = fmaf(s[r][48], v[48][lane], a0);
        obuf[(size_t)(widx * NN + r) * CC + head * HD + lane] = __float2bfloat16(a0 + a1);
    }
}

// ---------------- launch ----------------
extern "C" void kernel_launch(void* const* d_in, const int* in_sizes, int n_in,
                              void* d_out, int out_size)
{
    const float* x          = (const float*)d_in[0];
    const float* norm1_w    = (const float*)d_in[1];
    const float* norm1_b    = (const float*)d_in[2];
    const float* qkv_w      = (const float*)d_in[3];
    const float* qkv_b      = (const float*)d_in[4];
    const float* bias_table = (const float*)d_in[5];
    const float* proj_w     = (const float*)d_in[6];
    const float* proj_b     = (const float*)d_in[7];
    const float* norm2_w    = (const float*)d_in[8];
    const float* norm2_b    = (const float*)d_in[9];
    const float* fc1_w      = (const float*)d_in[10];
    const float* fc1_b      = (const float*)d_in[11];
    const float* fc2_w      = (const float*)d_in[12];
    const float* fc2_b      = (const float*)d_in[13];
    const float* attn_mask  = (const float*)d_in[14];
    const int*   rel_index  = (const int*)  d_in[15];
    float* out = (float*)d_out;

    __nv_bfloat16 *hwin, *obuf, *m1, *wt;
    float *qkv, *x1;
    cudaGetSymbolAddress((void**)&hwin, g_hwin);
    cudaGetSymbolAddress((void**)&qkv,  g_qkv);
    cudaGetSymbolAddress((void**)&obuf, g_obuf);
    cudaGetSymbolAddress((void**)&x1,   g_x1);
    cudaGetSymbolAddress((void**)&m1,   g_m1);
    cudaGetSymbolAddress((void**)&wt,   g_wt);

    // 0. weights -> bf16 transposed [N][K]
    round_wt_kernel<<<(W_TOTAL + 255) / 256, 256>>>(qkv_w, proj_w, fc1_w, fc2_w, wt);

    // 1. LN1 + shift + window partition -> bf16
    ln_kernel<true><<<TOK / 8, 256>>>(x, norm1_w, norm1_b, hwin);

    // 2. QKV gemm -> fp32
    gemm_bf<192,0><<<dim3(9, TOK / 128), 128>>>(hwin, wt + W_QKV, qkv_b, nullptr, qkv, nullptr, 576);

    // 3. attention -> bf16
    attn_kernel<<<(TOK / NN) * HEADS, 128>>>(qkv, bias_table, rel_index, attn_mask, obuf);

    // 4. proj gemm + window-reverse scatter + residual(x) -> x1 (fp32)
    gemm_bf<192,2><<<dim3(3, TOK / 128), 128>>>(obuf, wt + W_PROJ, proj_b, x, x1, nullptr, CC);

    // 5. LN2 -> bf16
    ln_kernel<false><<<TOK / 8, 256>>>(x1, norm2_w, norm2_b, hwin);

    // 6. fc1 + gelu -> bf16
    gemm_bf<192,1><<<dim3(12, TOK / 128), 128>>>(hwin, wt + W_FC1, fc1_b, nullptr, nullptr, m1, HID);

    // 7. fc2 + residual(x1) -> out (fp32)
    gemm_bf<768,3><<<dim3(3, TOK / 128), 128>>>(m1, wt + W_FC2, fc2_b, x1, out, nullptr, CC);
}

// round 17
// speedup vs baseline: 1.5384x; 1.3925x over previous
#include <cuda_runtime.h>
#include <cuda_bf16.h>
#include <stdint.h>
#include <math.h>

// ---------------- problem constants ----------------
#define BB 32
#define HH 56
#define WW 56
#define CC 192
#define WS 7
#define SHIFT 3
#define HEADS 6
#define HID 768
#define NN 49
#define NWIN 64
#define HD 32
#define TOK (BB*HH*WW)   // 100352

// weight scratch offsets (elements)
#define W_QKV 0
#define W_PROJ 110592
#define W_FC1 147456
#define W_FC2 294912
#define W_TOTAL 442368

// ---------------- scratch ----------------
__device__ __nv_bfloat16 g_hwin[(size_t)TOK * CC];
__device__ __nv_bfloat16 g_qkv [(size_t)TOK * 3 * CC];   // bf16 now
__device__ __nv_bfloat16 g_obuf[(size_t)TOK * CC];
__device__ float         g_x1  [(size_t)TOK * CC];
__device__ __nv_bfloat16 g_m1  [(size_t)TOK * HID];
__device__ __nv_bfloat16 g_wt  [W_TOTAL];
__device__ float         g_bm  [(size_t)HEADS * NWIN * NN * 50];

__device__ __forceinline__ void cp16(void* sp, const void* gp) {
    unsigned int sa = (unsigned int)__cvta_generic_to_shared(sp);
    asm volatile("cp.async.ca.shared.global [%0], [%1], 16;" :: "r"(sa), "l"(gp));
}

__device__ __forceinline__ __nv_bfloat162 pack_bf2(float lo, float hi) {
    return __floats2bfloat162_rn(lo, hi);
}

__device__ __forceinline__ void ldsm4(unsigned int& r0, unsigned int& r1,
                                      unsigned int& r2, unsigned int& r3,
                                      unsigned int addr) {
    asm volatile("ldmatrix.sync.aligned.m8n8.x4.shared.b16 {%0,%1,%2,%3}, [%4];"
                 : "=r"(r0), "=r"(r1), "=r"(r2), "=r"(r3) : "r"(addr));
}
__device__ __forceinline__ void ldsm4t(unsigned int& r0, unsigned int& r1,
                                       unsigned int& r2, unsigned int& r3,
                                       unsigned int addr) {
    asm volatile("ldmatrix.sync.aligned.m8n8.x4.trans.shared.b16 {%0,%1,%2,%3}, [%4];"
                 : "=r"(r0), "=r"(r1), "=r"(r2), "=r"(r3) : "r"(addr));
}

#define MMA_BF(acc, A0, A1, A2, A3, B0, B1)                                 \
    asm("mma.sync.aligned.m16n8k16.row.col.f32.bf16.bf16.f32 "              \
        "{%0,%1,%2,%3}, {%4,%5,%6,%7}, {%8,%9}, {%0,%1,%2,%3};"             \
        : "+f"(acc[0]), "+f"(acc[1]), "+f"(acc[2]), "+f"(acc[3])            \
        : "r"(A0), "r"(A1), "r"(A2), "r"(A3), "r"(B0), "r"(B1))

// ---------------- weight transpose + bf16 ----------------
__global__ void round_wt_kernel(const float* __restrict__ a, const float* __restrict__ b,
                                const float* __restrict__ c, const float* __restrict__ d,
                                __nv_bfloat16* __restrict__ o)
{
    int i = blockIdx.x * 256 + threadIdx.x;
    if (i >= W_TOTAL) return;
    const float* src; int off, K_, N_;
    if (i < W_PROJ)      { src = a; off = W_QKV;  K_ = 192; N_ = 576; }
    else if (i < W_FC1)  { src = b; off = W_PROJ; K_ = 192; N_ = 192; }
    else if (i < W_FC2)  { src = c; off = W_FC1;  K_ = 192; N_ = 768; }
    else                 { src = d; off = W_FC2;  K_ = 768; N_ = 192; }
    int il = i - off;
    int n = il / K_, k = il % K_;
    o[i] = __float2bfloat16(src[(size_t)k * N_ + n]);
}

// ---------------- bias+mask fold: bm[head][wi][i][j(pad 50)] ----------------
__global__ void bm_kernel(const float* __restrict__ bias_table,
                          const int*   __restrict__ rel_index,
                          const float* __restrict__ mask,
                          float* __restrict__ bm)
{
    int idx = blockIdx.x * 256 + threadIdx.x;
    if (idx >= HEADS * NWIN * NN * NN) return;
    int head = idx / (NWIN * NN * NN);
    int r    = idx % (NWIN * NN * NN);
    int wi   = r / (NN * NN);
    int ij   = r % (NN * NN);
    bm[((size_t)(head * NWIN + wi) * NN + ij / NN) * 50 + ij % NN] =
        bias_table[rel_index[ij] * HEADS + head] + mask[(size_t)wi * NN * NN + ij];
}

// ---------------- LayerNorm (1 warp/row) -> bf16 ----------------
template<bool WINDOW_MAP>
__global__ void ln_kernel(const float* __restrict__ x,
                          const float* __restrict__ w,
                          const float* __restrict__ b,
                          __nv_bfloat16* __restrict__ out)
{
    int row  = blockIdx.x * (blockDim.x >> 5) + (threadIdx.x >> 5);
    int lane = threadIdx.x & 31;
    if (row >= TOK) return;

    int src;
    if (WINDOW_MAP) {
        int widx = row / NN;
        int n    = row % NN;
        int bb   = widx / NWIN;
        int wi   = widx % NWIN;
        int wh   = wi / (WW / WS);
        int ww   = wi % (WW / WS);
        int hs   = wh * WS + n / WS;
        int ws   = ww * WS + n % WS;
        int h0   = (hs + SHIFT) % HH;
        int w0   = (ws + SHIFT) % WW;
        src = (bb * HH + h0) * WW + w0;
    } else {
        src = row;
    }

    const float* xr = x + (size_t)src * CC;
    float2 v[3];
    float s = 0.f;
#pragma unroll
    for (int i = 0; i < 3; i++) {
        v[i] = *(const float2*)(xr + 2 * lane + 64 * i);
        s += v[i].x + v[i].y;
    }
#pragma unroll
    for (int o = 16; o; o >>= 1) s += __shfl_xor_sync(0xffffffffu, s, o);
    float mu = s * (1.0f / CC);
    float vs = 0.f;
#pragma unroll
    for (int i = 0; i < 3; i++) {
        float d0 = v[i].x - mu, d1 = v[i].y - mu;
        vs += d0 * d0 + d1 * d1;
    }
#pragma unroll
    for (int o = 16; o; o >>= 1) vs += __shfl_xor_sync(0xffffffffu, vs, o);
    float rstd = rsqrtf(vs * (1.0f / CC) + 1e-5f);

    __nv_bfloat16* orow = out + (size_t)row * CC;
#pragma unroll
    for (int i = 0; i < 3; i++) {
        int c = 2 * lane + 64 * i;
        float y0 = (v[i].x - mu) * rstd * w[c]     + b[c];
        float y1 = (v[i].y - mu) * rstd * w[c + 1] + b[c + 1];
        *(__nv_bfloat162*)(orow + c) = pack_bf2(y0, y1);
    }
}

// ---------------- bf16 tensor-core GEMM (round-15 proven) ----------------
// EPI: 0 bias->f32; 1 bias+gelu->bf16; 2 bias+res(gather)+scatter->f32; 3 bias+res->f32; 4 bias->bf16
template<int K, int EPI>
__global__ __launch_bounds__(128)
void gemm_bf(const __nv_bfloat16* __restrict__ A, const __nv_bfloat16* __restrict__ Wt,
             const float* __restrict__ bias, const float* __restrict__ aux,
             float* __restrict__ Cf, __nv_bfloat16* __restrict__ Cb, int Nc)
{
    __shared__ __align__(16) __nv_bfloat16 As[2][128 * 40];
    __shared__ __align__(16) __nv_bfloat16 Bs[2][64 * 40];

    int tid  = threadIdx.x;
    int lane = tid & 31;
    int warp = tid >> 5;
    int g = lane >> 2;
    int q = lane & 3;
    int wm = (warp >> 1) * 64;
    int wn = (warp & 1) * 32;
    int m0 = blockIdx.y * 128;
    int n0 = blockIdx.x * 64;

    int a_m  = tid >> 2;
    int a_kc = (tid & 3) * 8;
    int b_n  = tid >> 2;
    int b_kc = (tid & 3) * 8;

    int a_ld_off = (wm + (lane & 15)) * 40 + (lane >> 4) * 8;
    int b_ld_off = (wn + (lane >> 4) * 8 + (lane & 7)) * 40
                 + ((lane >> 3) & 1) * 8;

    float acc[4][4][4] = {};
    constexpr int KT = K / 32;

#define ISSUE(kt, st) do {                                                          \
        __nv_bfloat16* as_ = As[st];                                                \
        __nv_bfloat16* bs_ = Bs[st];                                                \
        _Pragma("unroll")                                                           \
        for (int j = 0; j < 4; j++) {                                               \
            int m_ = a_m + 32 * j;                                                  \
            cp16(as_ + m_ * 40 + a_kc, A + (size_t)(m0 + m_) * K + (kt) * 32 + a_kc); \
        }                                                                           \
        _Pragma("unroll")                                                           \
        for (int j = 0; j < 2; j++) {                                               \
            int n_ = b_n + 32 * j;                                                  \
            cp16(bs_ + n_ * 40 + b_kc, Wt + (size_t)(n0 + n_) * K + (kt) * 32 + b_kc); \
        }                                                                           \
        asm volatile("cp.async.commit_group;");                                     \
    } while (0)

    ISSUE(0, 0);
    for (int kt = 0; kt < KT; kt++) {
        if (kt + 1 < KT) { ISSUE(kt + 1, (kt + 1) & 1); }
        else             { asm volatile("cp.async.commit_group;"); }
        asm volatile("cp.async.wait_group 1;");
        __syncthreads();

        unsigned int as_base = (unsigned int)__cvta_generic_to_shared(As[kt & 1]);
        unsigned int bs_base = (unsigned int)__cvta_generic_to_shared(Bs[kt & 1]);
#pragma unroll
        for (int ks = 0; ks < 2; ks++) {
            unsigned int a[4][4], b[4][2];
#pragma unroll
            for (int mi = 0; mi < 4; mi++)
                ldsm4(a[mi][0], a[mi][1], a[mi][2], a[mi][3],
                      as_base + 2u * (a_ld_off + mi * 16 * 40 + ks * 16));
            ldsm4(b[0][0], b[0][1], b[1][0], b[1][1],
                  bs_base + 2u * (b_ld_off + ks * 16));
            ldsm4(b[2][0], b[2][1], b[3][0], b[3][1],
                  bs_base + 2u * (b_ld_off + 16 * 40 + ks * 16));
#pragma unroll
            for (int mi = 0; mi < 4; mi++)
#pragma unroll
                for (int ni = 0; ni < 4; ni++)
                    MMA_BF(acc[mi][ni], a[mi][0], a[mi][1], a[mi][2], a[mi][3],
                           b[ni][0], b[ni][1]);
        }
        __syncthreads();
    }
#undef ISSUE

#pragma unroll
    for (int mi = 0; mi < 4; mi++) {
#pragma unroll
        for (int h = 0; h < 2; h++) {
            int row = m0 + wm + mi * 16 + g + h * 8;
            size_t base;
            if (EPI == 2) {
                int widx = row / NN;
                int n    = row % NN;
                int bimg = widx >> 6;
                int wi   = widx & 63;
                int hs = (wi >> 3) * WS + n / WS;
                int ws = (wi & 7) * WS + n % WS;
                int h2 = hs + SHIFT; if (h2 >= HH) h2 -= HH;
                int w2 = ws + SHIFT; if (w2 >= WW) w2 -= WW;
                base = (size_t)((bimg * HH + h2) * WW + w2) * CC;
            } else {
                base = (size_t)row * Nc;
            }
#pragma unroll
            for (int ni = 0; ni < 4; ni++) {
                int col = n0 + wn + ni * 8 + 2 * q;
                float c0 = acc[mi][ni][2 * h + 0] + bias[col];
                float c1 = acc[mi][ni][2 * h + 1] + bias[col + 1];
                size_t idx = base + col;
                if (EPI == 1 || EPI == 4) {
                    if (EPI == 1) {
                        c0 = 0.5f * c0 * (1.0f + erff(c0 * 0.70710678118654752f));
                        c1 = 0.5f * c1 * (1.0f + erff(c1 * 0.70710678118654752f));
                    }
                    *(__nv_bfloat162*)(Cb + idx) = pack_bf2(c0, c1);
                } else {
                    if (EPI == 2 || EPI == 3) {
                        float2 av = *(const float2*)(aux + idx);
                        c0 += av.x; c1 += av.y;
                    }
                    float2 o; o.x = c0; o.y = c1;
                    *(float2*)(Cf + idx) = o;
                }
            }
        }
    }
}

// ---------------- tensor-core attention: block (window, head), 4 warps ----------------
#define QKST 40
#define PST  72
__global__ __launch_bounds__(128)
void attn_tc(const __nv_bfloat16* __restrict__ qkv,
             const float* __restrict__ bm,
             __nv_bfloat16* __restrict__ obuf)
{
    int head = blockIdx.x % HEADS;
    int widx = blockIdx.x / HEADS;
    int wi   = widx & 63;

    __shared__ __align__(16) __nv_bfloat16 Qs[64 * QKST];
    __shared__ __align__(16) __nv_bfloat16 Ks[64 * QKST];
    __shared__ __align__(16) __nv_bfloat16 Vs[64 * QKST];
    __shared__ __align__(16) __nv_bfloat16 Ps[64 * PST];

    int tid  = threadIdx.x;
    int warp = tid >> 5;
    int lane = tid & 31;
    int g = lane >> 2;
    int q = lane & 3;
    const float scale = 0.17677669529663687f;

    // ---- zero pad rows (49..63) of Q/K/V and all of P ----
    {
        unsigned int* qz = (unsigned int*)(Qs + 49 * QKST);
        unsigned int* kz = (unsigned int*)(Ks + 49 * QKST);
        unsigned int* vz = (unsigned int*)(Vs + 49 * QKST);
        for (int i = tid; i < 15 * QKST / 2; i += 128) { qz[i] = 0; kz[i] = 0; vz[i] = 0; }
        unsigned int* pz = (unsigned int*)Ps;
        for (int i = tid; i < 64 * PST / 2; i += 128) pz[i] = 0;
    }

    // ---- cp.async fill Q,K,V (bf16, no conversion) ----
    for (int u = tid; u < NN * 12; u += 128) {
        int i  = u / 12;
        int c  = u % 12;
        int m  = c >> 2;          // 0=Q,1=K,2=V
        int ch = c & 3;           // 16B chunk
        const __nv_bfloat16* src = qkv + (size_t)(widx * NN + i) * (3 * CC)
                                 + m * CC + head * HD + ch * 8;
        __nv_bfloat16* dst = (m == 0 ? Qs : (m == 1 ? Ks : Vs)) + i * QKST + ch * 8;
        cp16(dst, src);
    }
    asm volatile("cp.async.commit_group;");
    asm volatile("cp.async.wait_group 0;");
    __syncthreads();

    unsigned int qbase = (unsigned int)__cvta_generic_to_shared(Qs);
    unsigned int kbase = (unsigned int)__cvta_generic_to_shared(Ks);
    unsigned int vbase = (unsigned int)__cvta_generic_to_shared(Vs);
    unsigned int pbase = (unsigned int)__cvta_generic_to_shared(Ps);

    int mrow = warp * 16;
    int a_off = (mrow + (lane & 15)) * QKST + (lane >> 4) * 8;

    // ---- S = Q @ K^T ----
    float c[7][4] = {};
#pragma unroll
    for (int ks = 0; ks < 2; ks++) {
        unsigned int a0, a1, a2, a3;
        ldsm4(a0, a1, a2, a3, qbase + 2u * (a_off + ks * 16));
        int b_off = ((lane >> 4) * 8 + (lane & 7)) * QKST + ((lane >> 3) & 1) * 8 + ks * 16;
#pragma unroll
        for (int t = 0; t < 4; t++) {
            unsigned int b0, b1, b2, b3;
            ldsm4(b0, b1, b2, b3, kbase + 2u * (b_off + t * 16 * QKST));
            MMA_BF(c[2 * t], a0, a1, a2, a3, b0, b1);
            if (2 * t + 1 < 7) MMA_BF(c[2 * t + 1], a0, a1, a2, a3, b2, b3);
        }
    }

    // ---- scale + bias/mask + register softmax (rows r0, r1) ----
    int r0 = mrow + g, r1 = r0 + 8;
    const float* bmb = bm + (size_t)(head * NWIN + wi) * NN * 50;
#pragma unroll
    for (int ni = 0; ni < 7; ni++) {
        int col = ni * 8 + 2 * q;
        if (r0 < NN) {
            if (col + 1 < NN) {
                float2 bv = *(const float2*)(bmb + r0 * 50 + col);
                c[ni][0] = c[ni][0] * scale + bv.x;
                c[ni][1] = c[ni][1] * scale + bv.y;
            } else if (col < NN) {
                c[ni][0] = c[ni][0] * scale + bmb[r0 * 50 + col];
                c[ni][1] = -1e30f;
            } else { c[ni][0] = -1e30f; c[ni][1] = -1e30f; }
        } else { c[ni][0] = -1e30f; c[ni][1] = -1e30f; }
        if (r1 < NN) {
            if (col + 1 < NN) {
                float2 bv = *(const float2*)(bmb + r1 * 50 + col);
                c[ni][2] = c[ni][2] * scale + bv.x;
                c[ni][3] = c[ni][3] * scale + bv.y;
            } else if (col < NN) {
                c[ni][2] = c[ni][2] * scale + bmb[r1 * 50 + col];
                c[ni][3] = -1e30f;
            } else { c[ni][2] = -1e30f; c[ni][3] = -1e30f; }
        } else { c[ni][2] = -1e30f; c[ni][3] = -1e30f; }
    }
    float mx0 = -1e30f, mx1 = -1e30f;
#pragma unroll
    for (int ni = 0; ni < 7; ni++) {
        mx0 = fmaxf(mx0, fmaxf(c[ni][0], c[ni][1]));
        mx1 = fmaxf(mx1, fmaxf(c[ni][2], c[ni][3]));
    }
    mx0 = fmaxf(mx0, __shfl_xor_sync(0xffffffffu, mx0, 1));
    mx0 = fmaxf(mx0, __shfl_xor_sync(0xffffffffu, mx0, 2));
    mx1 = fmaxf(mx1, __shfl_xor_sync(0xffffffffu, mx1, 1));
    mx1 = fmaxf(mx1, __shfl_xor_sync(0xffffffffu, mx1, 2));
    float s0 = 0.f, s1 = 0.f;
#pragma unroll
    for (int ni = 0; ni < 7; ni++) {
        c[ni][0] = __expf(c[ni][0] - mx0);
        c[ni][1] = __expf(c[ni][1] - mx0);
        c[ni][2] = __expf(c[ni][2] - mx1);
        c[ni][3] = __expf(c[ni][3] - mx1);
        s0 += c[ni][0] + c[ni][1];
        s1 += c[ni][2] + c[ni][3];
    }
    s0 += __shfl_xor_sync(0xffffffffu, s0, 1);
    s0 += __shfl_xor_sync(0xffffffffu, s0, 2);
    s1 += __shfl_xor_sync(0xffffffffu, s1, 1);
    s1 += __shfl_xor_sync(0xffffffffu, s1, 2);
    float i0 = (s0 > 0.f) ? 1.0f / s0 : 0.f;
    float i1 = (s1 > 0.f) ? 1.0f / s1 : 0.f;

    // ---- store P (bf16) ----
#pragma unroll
    for (int ni = 0; ni < 7; ni++) {
        int col = ni * 8 + 2 * q;
        *(__nv_bfloat162*)&Ps[r0 * PST + col] = pack_bf2(c[ni][0] * i0, c[ni][1] * i0);
        *(__nv_bfloat162*)&Ps[r1 * PST + col] = pack_bf2(c[ni][2] * i1, c[ni][3] * i1);
    }
    __syncwarp();

    // ---- O = P @ V (V transposed in-flight) ----
    float o[4][4] = {};
    int pa_off = (mrow + (lane & 15)) * PST + (lane >> 4) * 8;
#pragma unroll
    for (int ks = 0; ks < 4; ks++) {
        unsigned int a0, a1, a2, a3;
        ldsm4(a0, a1, a2, a3, pbase + 2u * (pa_off + ks * 16));
        int vb_off = (ks * 16 + ((lane >> 3) & 1) * 8 + (lane & 7)) * QKST + (lane >> 4) * 8;
#pragma unroll
        for (int t = 0; t < 2; t++) {
            unsigned int b0, b1, b2, b3;
            ldsm4t(b0, b1, b2, b3, vbase + 2u * (vb_off + t * 16));
            MMA_BF(o[2 * t],     a0, a1, a2, a3, b0, b1);
            MMA_BF(o[2 * t + 1], a0, a1, a2, a3, b2, b3);
        }
    }

    // ---- write O (bf16) ----
#pragma unroll
    for (int ni = 0; ni < 4; ni++) {
        int col = head * HD + ni * 8 + 2 * q;
        if (r0 < NN)
            *(__nv_bfloat162*)&obuf[(size_t)(widx * NN + r0) * CC + col] =
                pack_bf2(o[ni][0], o[ni][1]);
        if (r1 < NN)
            *(__nv_bfloat162*)&obuf[(size_t)(widx * NN + r1) * CC + col] =
                pack_bf2(o[ni][2], o[ni][3]);
    }
}

// ---------------- launch ----------------
extern "C" void kernel_launch(void* const* d_in, const int* in_sizes, int n_in,
                              void* d_out, int out_size)
{
    const float* x          = (const float*)d_in[0];
    const float* norm1_w    = (const float*)d_in[1];
    const float* norm1_b    = (const float*)d_in[2];
    const float* qkv_w      = (const float*)d_in[3];
    const float* qkv_b      = (const float*)d_in[4];
    const float* bias_table = (const float*)d_in[5];
    const float* proj_w     = (const float*)d_in[6];
    const float* proj_b     = (const float*)d_in[7];
    const float* norm2_w    = (const float*)d_in[8];
    const float* norm2_b    = (const float*)d_in[9];
    const float* fc1_w      = (const float*)d_in[10];
    const float* fc1_b      = (const float*)d_in[11];
    const float* fc2_w      = (const float*)d_in[12];
    const float* fc2_b      = (const float*)d_in[13];
    const float* attn_mask  = (const float*)d_in[14];
    const int*   rel_index  = (const int*)  d_in[15];
    float* out = (float*)d_out;

    __nv_bfloat16 *hwin, *qkvb, *obuf, *m1, *wt;
    float *x1, *bm;
    cudaGetSymbolAddress((void**)&hwin, g_hwin);
    cudaGetSymbolAddress((void**)&qkvb, g_qkv);
    cudaGetSymbolAddress((void**)&obuf, g_obuf);
    cudaGetSymbolAddress((void**)&x1,   g_x1);
    cudaGetSymbolAddress((void**)&m1,   g_m1);
    cudaGetSymbolAddress((void**)&wt,   g_wt);
    cudaGetSymbolAddress((void**)&bm,   g_bm);

    // 0. weights -> bf16 transposed; fold bias+mask
    round_wt_kernel<<<(W_TOTAL + 255) / 256, 256>>>(qkv_w, proj_w, fc1_w, fc2_w, wt);
    bm_kernel<<<(HEADS * NWIN * NN * NN + 255) / 256, 256>>>(bias_table, rel_index, attn_mask, bm);

    // 1. LN1 + shift + window partition -> bf16
    ln_kernel<true><<<TOK / 8, 256>>>(x, norm1_w, norm1_b, hwin);

    // 2. QKV gemm -> bf16
    gemm_bf<192,4><<<dim3(9, TOK / 128), 128>>>(hwin, wt + W_QKV, qkv_b, nullptr, nullptr, qkvb, 576);

    // 3. tensor-core attention -> bf16
    attn_tc<<<(TOK / NN) * HEADS, 128>>>(qkvb, bm, obuf);

    // 4. proj gemm + window-reverse scatter + residual(x) -> x1 (fp32)
    gemm_bf<192,2><<<dim3(3, TOK / 128), 128>>>(obuf, wt + W_PROJ, proj_b, x, x1, nullptr, CC);

    // 5. LN2 -> bf16
    ln_kernel<false><<<TOK / 8, 256>>>(x1, norm2_w, norm2_b, hwin);

    // 6. fc1 + gelu -> bf16
    gemm_bf<192,1><<<dim3(12, TOK / 128), 128>>>(hwin, wt + W_FC1, fc1_b, nullptr, nullptr, m1, HID);

    // 7. fc2 + residual(x1) -> out (fp32)
    gemm_bf<768,3><<<dim3(3, TOK / 128), 128>>>(m1, wt + W_FC2, fc2_b, x1, out, nullptr, CC);
}